// round 3
// baseline (speedup 1.0000x reference)
#include <cuda_runtime.h>
#include <cuda_bf16.h>
#include <cstdint>

// Problem constants
#define BB 4
#define LL 1024
#define DD 768
#define HH 12
#define HDIM 64
#define SCALING 0.125f   // 64^-0.5
#define TD 68            // padded smem row stride (floats): 16B aligned, odd-bank

// Scratch (device globals; no cudaMalloc allowed)
__device__ float g_qkv[BB * LL * 3 * DD];    // [B*L, 2304]  (q | k | v)
__device__ float g_attn[BB * LL * DD];       // [B*L, 768]

// ---------------------------------------------------------------------------
// GEMM: C[M,N] = A[M,K] @ W[N,K]^T + bias[N]
// Both A and W are K-major (contiguous along K) -> coalesced global loads.
// 64x64 block tile, BK=16, 256 threads, 4x4 per-thread micro tile.
// Smem stored transposed [BK][64+pad] so compute reads are float4:
//   a: broadcast (same addr across the 16 tx lanes), b: 16 contiguous float4s.
// ---------------------------------------------------------------------------
__global__ __launch_bounds__(256) void gemm_bias_kernel(
    const float* __restrict__ A, const float* __restrict__ W,
    const float* __restrict__ bias, float* __restrict__ C,
    int M, int N, int K)
{
    __shared__ float As[16][TD];
    __shared__ float Bs[16][TD];

    const int tid = threadIdx.x;
    const int tx = tid & 15;        // 0..15  -> N direction
    const int ty = tid >> 4;        // 0..15  -> M direction
    const int m0 = blockIdx.y * 64;
    const int n0 = blockIdx.x * 64;

    // cooperative load indices: each thread loads one float4 of A and W per k-step
    const int lr = tid >> 2;          // 0..63  row within tile
    const int lc = (tid & 3) * 4;     // 0,4,8,12 col within BK

    const float* Ap = A + (size_t)(m0 + lr) * K + lc;
    const float* Wp = W + (size_t)(n0 + lr) * K + lc;

    float acc[4][4];
#pragma unroll
    for (int i = 0; i < 4; i++)
#pragma unroll
        for (int j = 0; j < 4; j++) acc[i][j] = 0.0f;

    for (int k0 = 0; k0 < K; k0 += 16) {
        float4 a4 = *(const float4*)(Ap + k0);
        float4 b4 = *(const float4*)(Wp + k0);
        __syncthreads();   // previous iter's reads done before overwrite
        As[lc + 0][lr] = a4.x; As[lc + 1][lr] = a4.y;
        As[lc + 2][lr] = a4.z; As[lc + 3][lr] = a4.w;
        Bs[lc + 0][lr] = b4.x; Bs[lc + 1][lr] = b4.y;
        Bs[lc + 2][lr] = b4.z; Bs[lc + 3][lr] = b4.w;
        __syncthreads();

#pragma unroll
        for (int kk = 0; kk < 16; kk++) {
            float4 a = *(const float4*)&As[kk][4 * ty];
            float4 b = *(const float4*)&Bs[kk][4 * tx];
            float av[4] = {a.x, a.y, a.z, a.w};
            float bv[4] = {b.x, b.y, b.z, b.w};
#pragma unroll
            for (int i = 0; i < 4; i++)
#pragma unroll
                for (int j = 0; j < 4; j++) acc[i][j] += av[i] * bv[j];
        }
    }

    float4 bsv = *(const float4*)(bias + n0 + 4 * tx);
    float bvv[4] = {bsv.x, bsv.y, bsv.z, bsv.w};
#pragma unroll
    for (int i = 0; i < 4; i++) {
        float4 r;
        r.x = acc[i][0] + bvv[0];
        r.y = acc[i][1] + bvv[1];
        r.z = acc[i][2] + bvv[2];
        r.w = acc[i][3] + bvv[3];
        *(float4*)(C + (size_t)(m0 + 4 * ty + i) * N + n0 + 4 * tx) = r;
    }
}

// ---------------------------------------------------------------------------
// Flash attention with additive bias.
// One block = one (b, h, 64-query tile). 256 threads (16x16), 4x4 micro tiles.
// Online softmax; m/l kept redundantly across the 16 tx lanes of a row group
// (reductions via shfl within 16-lane groups make them consistent).
// Q/K/V read directly from the qkv buffer [B*L, 2304] (strided rows, float4).
// ---------------------------------------------------------------------------
__global__ __launch_bounds__(256) void attn_kernel(
    const float* __restrict__ qkv, const float* __restrict__ bias,
    float* __restrict__ out)
{
    extern __shared__ float sm[];
    float* Qs = sm;                 // [64][TD]
    float* Ks = Qs + 64 * TD;       // [64][TD]
    float* Vs = Ks + 64 * TD;       // [64][TD]
    float* Ps = Vs + 64 * TD;       // [64][TD]

    const int qt = blockIdx.x;      // 0..15
    const int h  = blockIdx.y;      // 0..11
    const int b  = blockIdx.z;      // 0..3
    const int tid = threadIdx.x;
    const int tx = tid & 15;
    const int ty = tid >> 4;
    const int q0 = qt * 64;

    // ---- load Q tile (scaled) ----
    {
        const float* qbase = qkv + ((size_t)(b * LL + q0)) * (3 * DD) + h * HDIM;
        for (int e = tid * 4; e < 64 * 64; e += 1024) {
            int r = e >> 6, c = e & 63;
            float4 v = *(const float4*)(qbase + (size_t)r * (3 * DD) + c);
            Qs[r * TD + c + 0] = v.x * SCALING;
            Qs[r * TD + c + 1] = v.y * SCALING;
            Qs[r * TD + c + 2] = v.z * SCALING;
            Qs[r * TD + c + 3] = v.w * SCALING;
        }
    }

    float o[4][4];
    float m[4], l[4];
#pragma unroll
    for (int i = 0; i < 4; i++) {
        m[i] = -1e30f; l[i] = 0.0f;
#pragma unroll
        for (int j = 0; j < 4; j++) o[i][j] = 0.0f;
    }

    const float* kbase = qkv + (size_t)b * LL * (3 * DD) + DD + h * HDIM;
    const float* vbase = qkv + (size_t)b * LL * (3 * DD) + 2 * DD + h * HDIM;
    const float* bbase = bias + (((size_t)(b * HH + h)) * LL + q0) * LL;

    for (int kt = 0; kt < LL / 64; kt++) {
        __syncthreads();   // prev iter's K/V/P reads done
        // ---- load K and V tiles ----
        for (int e = tid * 4; e < 64 * 64; e += 1024) {
            int r = e >> 6, c = e & 63;
            const size_t row = (size_t)(kt * 64 + r) * (3 * DD);
            float4 kv = *(const float4*)(kbase + row + c);
            Ks[r * TD + c + 0] = kv.x; Ks[r * TD + c + 1] = kv.y;
            Ks[r * TD + c + 2] = kv.z; Ks[r * TD + c + 3] = kv.w;
            float4 vv = *(const float4*)(vbase + row + c);
            Vs[r * TD + c + 0] = vv.x; Vs[r * TD + c + 1] = vv.y;
            Vs[r * TD + c + 2] = vv.z; Vs[r * TD + c + 3] = vv.w;
        }
        __syncthreads();

        // ---- S = Q K^T + bias (4x4 per thread) ----
        float s[4][4];
#pragma unroll
        for (int ii = 0; ii < 4; ii++) {
            float4 bv = *(const float4*)(bbase + (size_t)(4 * ty + ii) * LL + kt * 64 + 4 * tx);
            s[ii][0] = bv.x; s[ii][1] = bv.y; s[ii][2] = bv.z; s[ii][3] = bv.w;
        }
#pragma unroll 4
        for (int d4 = 0; d4 < 16; d4++) {
            float4 q4[4], k4[4];
#pragma unroll
            for (int ii = 0; ii < 4; ii++)
                q4[ii] = *(const float4*)&Qs[(4 * ty + ii) * TD + 4 * d4];
#pragma unroll
            for (int jj = 0; jj < 4; jj++)
                k4[jj] = *(const float4*)&Ks[(4 * tx + jj) * TD + 4 * d4];
#pragma unroll
            for (int ii = 0; ii < 4; ii++)
#pragma unroll
                for (int jj = 0; jj < 4; jj++)
                    s[ii][jj] += q4[ii].x * k4[jj].x + q4[ii].y * k4[jj].y
                               + q4[ii].z * k4[jj].z + q4[ii].w * k4[jj].w;
        }

        // ---- online softmax ----
#pragma unroll
        for (int ii = 0; ii < 4; ii++) {
            float mx = fmaxf(fmaxf(s[ii][0], s[ii][1]), fmaxf(s[ii][2], s[ii][3]));
#pragma unroll
            for (int off = 8; off; off >>= 1)
                mx = fmaxf(mx, __shfl_xor_sync(0xffffffffu, mx, off));
            float mnew = fmaxf(m[ii], mx);
            float corr = __expf(m[ii] - mnew);
            m[ii] = mnew;
            float ls = 0.0f;
#pragma unroll
            for (int jj = 0; jj < 4; jj++) {
                float p = __expf(s[ii][jj] - mnew);
                s[ii][jj] = p;
                ls += p;
            }
#pragma unroll
            for (int off = 8; off; off >>= 1)
                ls += __shfl_xor_sync(0xffffffffu, ls, off);
            l[ii] = l[ii] * corr + ls;
#pragma unroll
            for (int jj = 0; jj < 4; jj++) o[ii][jj] *= corr;
        }

        // ---- P -> shared ----
#pragma unroll
        for (int ii = 0; ii < 4; ii++) {
            float4 pv = make_float4(s[ii][0], s[ii][1], s[ii][2], s[ii][3]);
            *(float4*)&Ps[(4 * ty + ii) * TD + 4 * tx] = pv;
        }
        __syncthreads();

        // ---- O += P @ V ----
#pragma unroll 8
        for (int j = 0; j < 64; j++) {
            float4 v4 = *(const float4*)&Vs[j * TD + 4 * tx];
            float p0 = Ps[(4 * ty + 0) * TD + j];
            float p1 = Ps[(4 * ty + 1) * TD + j];
            float p2 = Ps[(4 * ty + 2) * TD + j];
            float p3 = Ps[(4 * ty + 3) * TD + j];
            o[0][0] += p0 * v4.x; o[0][1] += p0 * v4.y; o[0][2] += p0 * v4.z; o[0][3] += p0 * v4.w;
            o[1][0] += p1 * v4.x; o[1][1] += p1 * v4.y; o[1][2] += p1 * v4.z; o[1][3] += p1 * v4.w;
            o[2][0] += p2 * v4.x; o[2][1] += p2 * v4.y; o[2][2] += p2 * v4.z; o[2][3] += p2 * v4.w;
            o[3][0] += p3 * v4.x; o[3][1] += p3 * v4.y; o[3][2] += p3 * v4.z; o[3][3] += p3 * v4.w;
        }
    }

    // ---- normalize + write out: out[b, q, h*64 + d] ----
#pragma unroll
    for (int ii = 0; ii < 4; ii++) {
        float inv = 1.0f / l[ii];
        float4 r = make_float4(o[ii][0] * inv, o[ii][1] * inv,
                               o[ii][2] * inv, o[ii][3] * inv);
        *(float4*)(out + ((size_t)(b * LL + q0 + 4 * ty + ii)) * DD + h * HDIM + 4 * tx) = r;
    }
}

// ---------------------------------------------------------------------------
// Launch
// ---------------------------------------------------------------------------
extern "C" void kernel_launch(void* const* d_in, const int* in_sizes, int n_in,
                              void* d_out, int out_size)
{
    const float* x         = (const float*)d_in[0];   // [B, L, D]
    const float* attn_bias = (const float*)d_in[1];   // [B, H, L, L]
    const float* w_in      = (const float*)d_in[2];   // [3D, D]
    const float* b_in      = (const float*)d_in[3];   // [3D]
    const float* w_out     = (const float*)d_in[4];   // [D, D]
    const float* b_out     = (const float*)d_in[5];   // [D]
    float* out = (float*)d_out;                       // [B, L, D]

    float* qkv = nullptr;
    float* attn = nullptr;
    cudaGetSymbolAddress((void**)&qkv,  g_qkv);
    cudaGetSymbolAddress((void**)&attn, g_attn);

    const int M = BB * LL;          // 4096

    // 1) QKV projection: [4096, 2304] = x @ w_in^T + b_in
    {
        dim3 grid((3 * DD) / 64, M / 64);
        gemm_bias_kernel<<<grid, 256>>>(x, w_in, b_in, qkv, M, 3 * DD, DD);
    }

    // 2) attention
    {
        const int smem = 4 * 64 * TD * (int)sizeof(float);   // 69632 B
        cudaFuncSetAttribute(attn_kernel,
                             cudaFuncAttributeMaxDynamicSharedMemorySize, smem);
        dim3 grid(LL / 64, HH, BB);
        attn_kernel<<<grid, 256, smem>>>(qkv, attn_bias, attn);
    }

    // 3) output projection: [4096, 768] = attn @ w_out^T + b_out
    {
        dim3 grid(DD / 64, M / 64);
        gemm_bias_kernel<<<grid, 256>>>(attn, w_out, b_out, out, M, DD, DD);
    }
}

// round 5
// speedup vs baseline: 1.5885x; 1.5885x over previous
#include <cuda_runtime.h>
#include <cuda_bf16.h>
#include <cstdint>

// Problem constants
#define BB 4
#define LL 1024
#define DD 768
#define HH 12
#define HDIM 64
#define SCALING 0.125f   // 64^-0.5

// smem strides (32-bit words), all chosen conflict-free for the fragment
// access patterns actually used:
//   GST=20 (BK=16 GEMM tiles):    bank = (20*gid+tig)%32 = 4*gid+tig  distinct
//   KST=68 (64-wide K/P tiles):   bank = (68*gid+tig)%32 = 4*gid+tig  distinct
//   VST=72 (64-wide V tile):      bank = (72*tig+gid)%32 = 8*tig+gid  distinct
#define GST 20
#define KST 68
#define VST 72

// Scratch (device globals; no cudaMalloc allowed)
__device__ float g_qkv[BB * LL * 3 * DD];    // [B*L, 2304]  (q | k | v)
__device__ float g_attn[BB * LL * DD];       // [B*L, 768]

// ---------------------------------------------------------------------------
// tf32 helpers
// ---------------------------------------------------------------------------
__device__ __forceinline__ uint32_t f2tf32(float x) {
    uint32_t u;
    asm("cvt.rna.tf32.f32 %0, %1;" : "=r"(u) : "f"(x));
    return u;
}

__device__ __forceinline__ void split_tf32(float x, uint32_t& hi, uint32_t& lo) {
    hi = f2tf32(x);
    float r = x - __uint_as_float(hi);
    lo = f2tf32(r);
}

__device__ __forceinline__ void mma_tf32(float c[4], const uint32_t a[4],
                                         const uint32_t b[2]) {
    asm volatile(
        "mma.sync.aligned.m16n8k8.row.col.f32.tf32.tf32.f32 "
        "{%0,%1,%2,%3}, {%4,%5,%6,%7}, {%8,%9}, {%0,%1,%2,%3};"
        : "+f"(c[0]), "+f"(c[1]), "+f"(c[2]), "+f"(c[3])
        : "r"(a[0]), "r"(a[1]), "r"(a[2]), "r"(a[3]), "r"(b[0]), "r"(b[1]));
}

// ---------------------------------------------------------------------------
// GEMM: C[M,N] = A[M,K] @ W[N,K]^T + bias[N], 3xTF32 split precision.
// Block tile 128(M) x 64(N), BK=16, 256 threads = 8 warps (4m x 2n),
// warp tile 32x32 = 2 m16-tiles x 4 n8-tiles.
// ---------------------------------------------------------------------------
__global__ __launch_bounds__(256) void gemm_tf32(
    const float* __restrict__ A, const float* __restrict__ W,
    const float* __restrict__ bias, float* __restrict__ C,
    int M, int N, int K)
{
    __shared__ uint32_t Ah[128][GST], Al[128][GST];
    __shared__ uint32_t Bh[64][GST],  Bl[64][GST];

    const int tid = threadIdx.x;
    const int lane = tid & 31, warp = tid >> 5;
    const int gid = lane >> 2, tig = lane & 3;
    const int wm = warp >> 1, wn = warp & 1;
    const int m0 = blockIdx.y * 128, n0 = blockIdx.x * 64;

    // cooperative load mapping (float4 per thread)
    const int lr = tid >> 2;            // 0..63
    const int lc = (tid & 3) * 4;       // 0,4,8,12

    const float* Ap0 = A + (size_t)(m0 + lr) * K + lc;
    const float* Ap1 = A + (size_t)(m0 + 64 + lr) * K + lc;
    const float* Wp  = W + (size_t)(n0 + lr) * K + lc;

    float acc[2][4][4];
#pragma unroll
    for (int mt = 0; mt < 2; mt++)
#pragma unroll
        for (int nt = 0; nt < 4; nt++)
#pragma unroll
            for (int j = 0; j < 4; j++) acc[mt][nt][j] = 0.0f;

    for (int k0 = 0; k0 < K; k0 += 16) {
        float4 a0 = *(const float4*)(Ap0 + k0);
        float4 a1 = *(const float4*)(Ap1 + k0);
        float4 b0 = *(const float4*)(Wp + k0);
        __syncthreads();
        split_tf32(a0.x, Ah[lr][lc + 0], Al[lr][lc + 0]);
        split_tf32(a0.y, Ah[lr][lc + 1], Al[lr][lc + 1]);
        split_tf32(a0.z, Ah[lr][lc + 2], Al[lr][lc + 2]);
        split_tf32(a0.w, Ah[lr][lc + 3], Al[lr][lc + 3]);
        split_tf32(a1.x, Ah[64 + lr][lc + 0], Al[64 + lr][lc + 0]);
        split_tf32(a1.y, Ah[64 + lr][lc + 1], Al[64 + lr][lc + 1]);
        split_tf32(a1.z, Ah[64 + lr][lc + 2], Al[64 + lr][lc + 2]);
        split_tf32(a1.w, Ah[64 + lr][lc + 3], Al[64 + lr][lc + 3]);
        split_tf32(b0.x, Bh[lr][lc + 0], Bl[lr][lc + 0]);
        split_tf32(b0.y, Bh[lr][lc + 1], Bl[lr][lc + 1]);
        split_tf32(b0.z, Bh[lr][lc + 2], Bl[lr][lc + 2]);
        split_tf32(b0.w, Bh[lr][lc + 3], Bl[lr][lc + 3]);
        __syncthreads();

#pragma unroll
        for (int ks = 0; ks < 2; ks++) {
            const int kk = ks * 8;
            uint32_t bh[4][2], bl[4][2];
#pragma unroll
            for (int nt = 0; nt < 4; nt++) {
                const int n = wn * 32 + nt * 8 + gid;
                bh[nt][0] = Bh[n][kk + tig];
                bh[nt][1] = Bh[n][kk + tig + 4];
                bl[nt][0] = Bl[n][kk + tig];
                bl[nt][1] = Bl[n][kk + tig + 4];
            }
#pragma unroll
            for (int mt = 0; mt < 2; mt++) {
                const int r = wm * 32 + mt * 16;
                uint32_t ah[4] = {Ah[r + gid][kk + tig],     Ah[r + 8 + gid][kk + tig],
                                  Ah[r + gid][kk + tig + 4], Ah[r + 8 + gid][kk + tig + 4]};
                uint32_t al[4] = {Al[r + gid][kk + tig],     Al[r + 8 + gid][kk + tig],
                                  Al[r + gid][kk + tig + 4], Al[r + 8 + gid][kk + tig + 4]};
#pragma unroll
                for (int nt = 0; nt < 4; nt++) {
                    mma_tf32(acc[mt][nt], al, bh[nt]);
                    mma_tf32(acc[mt][nt], ah, bl[nt]);
                    mma_tf32(acc[mt][nt], ah, bh[nt]);
                }
            }
        }
    }

    // epilogue: C-frag rows gid / gid+8, cols tig*2, tig*2+1
#pragma unroll
    for (int mt = 0; mt < 2; mt++) {
#pragma unroll
        for (int nt = 0; nt < 4; nt++) {
            const int n = n0 + wn * 32 + nt * 8 + tig * 2;
            const float2 bs = *(const float2*)(bias + n);
            const int r = m0 + wm * 32 + mt * 16 + gid;
            float2 v0 = make_float2(acc[mt][nt][0] + bs.x, acc[mt][nt][1] + bs.y);
            float2 v1 = make_float2(acc[mt][nt][2] + bs.x, acc[mt][nt][3] + bs.y);
            *(float2*)(C + (size_t)r * N + n) = v0;
            *(float2*)(C + (size_t)(r + 8) * N + n) = v1;
        }
    }
}

// ---------------------------------------------------------------------------
// Flash attention with additive bias, 3xTF32 mma.
// One block = (b, h, 64-query tile), 128 threads = 4 warps, warp owns 16 rows.
// Q fragments live in registers (loop-invariant). K tile smem is reused for P.
// ---------------------------------------------------------------------------
__global__ __launch_bounds__(128) void attn_tf32(
    const float* __restrict__ qkv, const float* __restrict__ bias,
    float* __restrict__ out)
{
    extern __shared__ uint32_t sm[];
    uint32_t* KPh = sm;                 // [64][KST]  K tile, later P tile
    uint32_t* KPl = KPh + 64 * KST;
    uint32_t* Vh  = KPl + 64 * KST;     // [64][VST]
    uint32_t* Vl  = Vh  + 64 * VST;

    const int tid = threadIdx.x;
    const int lane = tid & 31, warp = tid >> 5;
    const int gid = lane >> 2, tig = lane & 3;
    const int qt = blockIdx.x, h = blockIdx.y, b = blockIdx.z;
    const int q0 = qt * 64, wq = warp * 16;

    // ---- Q fragments in registers (scaled, hi/lo split) ----
    uint32_t qh[8][4], ql[8][4];
    {
        const float* qr0 = qkv + (size_t)(b * LL + q0 + wq + gid) * (3 * DD) + h * HDIM;
        const float* qr1 = qr0 + (size_t)8 * (3 * DD);
#pragma unroll
        for (int ks = 0; ks < 8; ks++) {
            float v0 = qr0[ks * 8 + tig]     * SCALING;
            float v1 = qr1[ks * 8 + tig]     * SCALING;
            float v2 = qr0[ks * 8 + tig + 4] * SCALING;
            float v3 = qr1[ks * 8 + tig + 4] * SCALING;
            split_tf32(v0, qh[ks][0], ql[ks][0]);
            split_tf32(v1, qh[ks][1], ql[ks][1]);
            split_tf32(v2, qh[ks][2], ql[ks][2]);
            split_tf32(v3, qh[ks][3], ql[ks][3]);
        }
    }

    float o[8][4];
#pragma unroll
    for (int dt = 0; dt < 8; dt++)
#pragma unroll
        for (int j = 0; j < 4; j++) o[dt][j] = 0.0f;
    float mr0 = -1e30f, mr1 = -1e30f, lr0 = 0.0f, lr1 = 0.0f;

    const float* kbase = qkv + (size_t)b * LL * (3 * DD) + DD + h * HDIM;
    const float* vbase = qkv + (size_t)b * LL * (3 * DD) + 2 * DD + h * HDIM;
    const float* bb = bias + ((size_t)(b * HH + h) * LL + q0 + wq) * LL;

    for (int kt = 0; kt < 16; kt++) {
        __syncthreads();   // prev iter's P/V reads done before overwrite
        // ---- load K, V tiles, split hi/lo ----
#pragma unroll
        for (int i = 0; i < 8; i++) {
            const int linear = tid + i * 128;          // 1024 float4
            const int r = linear >> 4, c4 = (linear & 15) * 4;
            const size_t grow = (size_t)(kt * 64 + r) * (3 * DD);
            float4 kv = *(const float4*)(kbase + grow + c4);
            split_tf32(kv.x, KPh[r * KST + c4 + 0], KPl[r * KST + c4 + 0]);
            split_tf32(kv.y, KPh[r * KST + c4 + 1], KPl[r * KST + c4 + 1]);
            split_tf32(kv.z, KPh[r * KST + c4 + 2], KPl[r * KST + c4 + 2]);
            split_tf32(kv.w, KPh[r * KST + c4 + 3], KPl[r * KST + c4 + 3]);
            float4 vv = *(const float4*)(vbase + grow + c4);
            split_tf32(vv.x, Vh[r * VST + c4 + 0], Vl[r * VST + c4 + 0]);
            split_tf32(vv.y, Vh[r * VST + c4 + 1], Vl[r * VST + c4 + 1]);
            split_tf32(vv.z, Vh[r * VST + c4 + 2], Vl[r * VST + c4 + 2]);
            split_tf32(vv.w, Vh[r * VST + c4 + 3], Vl[r * VST + c4 + 3]);
        }
        __syncthreads();

        // ---- S = bias, then S += Q @ K^T ----
        float s[8][4];
#pragma unroll
        for (int nt = 0; nt < 8; nt++) {
            const float* bp = bb + (size_t)gid * LL + kt * 64 + nt * 8 + tig * 2;
            float2 x0 = *(const float2*)bp;
            float2 x1 = *(const float2*)(bp + (size_t)8 * LL);
            s[nt][0] = x0.x; s[nt][1] = x0.y;
            s[nt][2] = x1.x; s[nt][3] = x1.y;
        }
#pragma unroll
        for (int ks = 0; ks < 8; ks++) {
            const int kk = ks * 8;
#pragma unroll
            for (int nt = 0; nt < 8; nt++) {
                const int n = nt * 8 + gid;
                uint32_t bh[2] = {KPh[n * KST + kk + tig], KPh[n * KST + kk + tig + 4]};
                uint32_t bl[2] = {KPl[n * KST + kk + tig], KPl[n * KST + kk + tig + 4]};
                mma_tf32(s[nt], ql[ks], bh);
                mma_tf32(s[nt], qh[ks], bl);
                mma_tf32(s[nt], qh[ks], bh);
            }
        }

        // ---- online softmax (rows gid and gid+8) ----
        float mx0 = -1e30f, mx1 = -1e30f;
#pragma unroll
        for (int nt = 0; nt < 8; nt++) {
            mx0 = fmaxf(mx0, fmaxf(s[nt][0], s[nt][1]));
            mx1 = fmaxf(mx1, fmaxf(s[nt][2], s[nt][3]));
        }
        mx0 = fmaxf(mx0, __shfl_xor_sync(0xffffffffu, mx0, 1));
        mx0 = fmaxf(mx0, __shfl_xor_sync(0xffffffffu, mx0, 2));
        mx1 = fmaxf(mx1, __shfl_xor_sync(0xffffffffu, mx1, 1));
        mx1 = fmaxf(mx1, __shfl_xor_sync(0xffffffffu, mx1, 2));
        const float mn0 = fmaxf(mr0, mx0), mn1 = fmaxf(mr1, mx1);
        const float c0 = __expf(mr0 - mn0), c1 = __expf(mr1 - mn1);
        mr0 = mn0; mr1 = mn1;
        float ls0 = 0.0f, ls1 = 0.0f;
#pragma unroll
        for (int nt = 0; nt < 8; nt++) {
            s[nt][0] = __expf(s[nt][0] - mn0);
            s[nt][1] = __expf(s[nt][1] - mn0);
            s[nt][2] = __expf(s[nt][2] - mn1);
            s[nt][3] = __expf(s[nt][3] - mn1);
            ls0 += s[nt][0] + s[nt][1];
            ls1 += s[nt][2] + s[nt][3];
        }
        ls0 += __shfl_xor_sync(0xffffffffu, ls0, 1);
        ls0 += __shfl_xor_sync(0xffffffffu, ls0, 2);
        ls1 += __shfl_xor_sync(0xffffffffu, ls1, 1);
        ls1 += __shfl_xor_sync(0xffffffffu, ls1, 2);
        lr0 = lr0 * c0 + ls0;
        lr1 = lr1 * c1 + ls1;
#pragma unroll
        for (int dt = 0; dt < 8; dt++) {
            o[dt][0] *= c0; o[dt][1] *= c0;
            o[dt][2] *= c1; o[dt][3] *= c1;
        }

        __syncthreads();   // all warps done reading K before overwrite with P
        // ---- write P (hi/lo) into KP buffer ----
#pragma unroll
        for (int nt = 0; nt < 8; nt++) {
            const int a0 = (wq + gid) * KST + nt * 8 + tig * 2;
            const int a1 = (wq + 8 + gid) * KST + nt * 8 + tig * 2;
            split_tf32(s[nt][0], KPh[a0],     KPl[a0]);
            split_tf32(s[nt][1], KPh[a0 + 1], KPl[a0 + 1]);
            split_tf32(s[nt][2], KPh[a1],     KPl[a1]);
            split_tf32(s[nt][3], KPh[a1 + 1], KPl[a1 + 1]);
        }
        __syncthreads();   // P visible to all warps

        // ---- O += P @ V ----
#pragma unroll
        for (int ks = 0; ks < 8; ks++) {
            const int jj = ks * 8;
            uint32_t ph[4] = {KPh[(wq + gid) * KST + jj + tig],
                              KPh[(wq + 8 + gid) * KST + jj + tig],
                              KPh[(wq + gid) * KST + jj + tig + 4],
                              KPh[(wq + 8 + gid) * KST + jj + tig + 4]};
            uint32_t pl[4] = {KPl[(wq + gid) * KST + jj + tig],
                              KPl[(wq + 8 + gid) * KST + jj + tig],
                              KPl[(wq + gid) * KST + jj + tig + 4],
                              KPl[(wq + 8 + gid) * KST + jj + tig + 4]};
#pragma unroll
            for (int dt = 0; dt < 8; dt++) {
                uint32_t vh2[2] = {Vh[(jj + tig) * VST + dt * 8 + gid],
                                   Vh[(jj + tig + 4) * VST + dt * 8 + gid]};
                uint32_t vl2[2] = {Vl[(jj + tig) * VST + dt * 8 + gid],
                                   Vl[(jj + tig + 4) * VST + dt * 8 + gid]};
                mma_tf32(o[dt], pl, vh2);
                mma_tf32(o[dt], ph, vl2);
                mma_tf32(o[dt], ph, vh2);
            }
        }
    }

    // ---- normalize + write out[b, q, h*64 + d] ----
    const float inv0 = 1.0f / lr0, inv1 = 1.0f / lr1;
#pragma unroll
    for (int dt = 0; dt < 8; dt++) {
        const int d = h * HDIM + dt * 8 + tig * 2;
        const int r0 = b * LL + q0 + wq + gid;
        float2 v0 = make_float2(o[dt][0] * inv0, o[dt][1] * inv0);
        float2 v1 = make_float2(o[dt][2] * inv1, o[dt][3] * inv1);
        *(float2*)(out + (size_t)r0 * DD + d) = v0;
        *(float2*)(out + (size_t)(r0 + 8) * DD + d) = v1;
    }
}

// ---------------------------------------------------------------------------
// Launch
// ---------------------------------------------------------------------------
extern "C" void kernel_launch(void* const* d_in, const int* in_sizes, int n_in,
                              void* d_out, int out_size)
{
    const float* x         = (const float*)d_in[0];   // [B, L, D]
    const float* attn_bias = (const float*)d_in[1];   // [B, H, L, L]
    const float* w_in      = (const float*)d_in[2];   // [3D, D]
    const float* b_in      = (const float*)d_in[3];   // [3D]
    const float* w_out     = (const float*)d_in[4];   // [D, D]
    const float* b_out     = (const float*)d_in[5];   // [D]
    float* out = (float*)d_out;                       // [B, L, D]

    float* qkv = nullptr;
    float* attn = nullptr;
    cudaGetSymbolAddress((void**)&qkv,  g_qkv);
    cudaGetSymbolAddress((void**)&attn, g_attn);

    const int M = BB * LL;          // 4096

    // 1) QKV projection: [4096, 2304] = x @ w_in^T + b_in
    {
        dim3 grid((3 * DD) / 64, M / 128);
        gemm_tf32<<<grid, 256>>>(x, w_in, b_in, qkv, M, 3 * DD, DD);
    }

    // 2) attention
    {
        const int smem = (2 * 64 * KST + 2 * 64 * VST) * (int)sizeof(uint32_t); // 71680
        cudaFuncSetAttribute(attn_tf32,
                             cudaFuncAttributeMaxDynamicSharedMemorySize, smem);
        dim3 grid(LL / 64, HH, BB);
        attn_tf32<<<grid, 128, smem>>>(qkv, attn_bias, attn);
    }

    // 3) output projection: [4096, 768] = attn @ w_out^T + b_out
    {
        dim3 grid(DD / 64, M / 128);
        gemm_tf32<<<grid, 256>>>(attn, w_out, b_out, out, M, DD, DD);
    }
}

// round 6
// speedup vs baseline: 2.8013x; 1.7635x over previous
#include <cuda_runtime.h>
#include <cuda_bf16.h>
#include <cstdint>

// Problem constants
#define BB 4
#define LL 1024
#define DD 768
#define HH 12
#define KW 384            // K/2 packed words (K = 768)
#define QKVW 1152         // 2304/2 words per qkv row
#define OW 384            // 768/2 words per attn-out row

// smem strides (32-bit words), conflict-free for fragment patterns:
//   GEMM tiles (16 words/row): stride 20 -> bank (20*gid+tig)%32 = 4*gid+tig distinct
//   Attn tiles (32 words/row): stride 36 -> bank 4*gid+tig distinct; ldmatrix rows 4*j+0..3 distinct
#define GS 20
#define AS 36

// Scratch (device globals; no cudaMalloc allowed)
__device__ uint32_t g_xh[4096 * KW],  g_xl[4096 * KW];
__device__ uint32_t g_wih[2304 * KW], g_wil[2304 * KW];
__device__ uint32_t g_woh[768 * KW],  g_wol[768 * KW];
__device__ uint32_t g_qh[4096 * QKVW], g_ql[4096 * QKVW];
__device__ uint32_t g_oh[4096 * OW],   g_ol[4096 * OW];

// ---------------------------------------------------------------------------
// helpers
// ---------------------------------------------------------------------------
__device__ __forceinline__ uint32_t pack2(float e0, float e1) {
    uint32_t d;  // low half = e0, high half = e1
    asm("cvt.rn.bf16x2.f32 %0, %1, %2;" : "=r"(d) : "f"(e1), "f"(e0));
    return d;
}

// split (e0,e1) into packed bf16 hi word + packed bf16 residual word
__device__ __forceinline__ void split2(float e0, float e1, uint32_t& h, uint32_t& l) {
    h = pack2(e0, e1);
    float h0 = __uint_as_float(h << 16);
    float h1 = __uint_as_float(h & 0xffff0000u);
    l = pack2(e0 - h0, e1 - h1);
}

__device__ __forceinline__ void mma_bf16(float c[4], const uint32_t a[4],
                                         const uint32_t b[2]) {
    asm volatile(
        "mma.sync.aligned.m16n8k16.row.col.f32.bf16.bf16.f32 "
        "{%0,%1,%2,%3}, {%4,%5,%6,%7}, {%8,%9}, {%0,%1,%2,%3};"
        : "+f"(c[0]), "+f"(c[1]), "+f"(c[2]), "+f"(c[3])
        : "r"(a[0]), "r"(a[1]), "r"(a[2]), "r"(a[3]), "r"(b[0]), "r"(b[1]));
}

__device__ __forceinline__ uint32_t sptr(const void* p) {
    return (uint32_t)__cvta_generic_to_shared(p);
}
__device__ __forceinline__ void cpa16(uint32_t s, const void* g) {
    asm volatile("cp.async.ca.shared.global [%0], [%1], 16;" :: "r"(s), "l"(g));
}
__device__ __forceinline__ void cp_commit() {
    asm volatile("cp.async.commit_group;" ::: "memory");
}
__device__ __forceinline__ void cp_wait1() {
    asm volatile("cp.async.wait_group 1;" ::: "memory");
}
__device__ __forceinline__ void cp_wait0() {
    asm volatile("cp.async.wait_group 0;" ::: "memory");
}
__device__ __forceinline__ void ldmx2t(uint32_t& r0, uint32_t& r1, uint32_t a) {
    asm volatile("ldmatrix.sync.aligned.m8n8.x2.trans.shared.b16 {%0,%1}, [%2];"
                 : "=r"(r0), "=r"(r1) : "r"(a));
}

// ---------------------------------------------------------------------------
// prepass: float -> packed bf16 hi/lo words
// ---------------------------------------------------------------------------
__global__ void splitpack_kernel(const float* __restrict__ in,
                                 uint32_t* __restrict__ h, uint32_t* __restrict__ l,
                                 int nw)
{
    int i = blockIdx.x * 256 + threadIdx.x;
    if (i < nw) {
        float2 v = ((const float2*)in)[i];
        uint32_t hh, ll;
        split2(v.x, v.y, hh, ll);
        h[i] = hh;
        l[i] = ll;
    }
}

// ---------------------------------------------------------------------------
// GEMM: C[M,N] = A[M,768] @ W[N,768]^T + bias[N], bf16 split x3 mma.
// Packed-word inputs. Block 128x128, BK=32 (16 words), 256 thr = 8 warps (2x4),
// warp tile 64x32. 2-stage cp.async pipeline.
// If PACKED_OUT: write split-packed hi/lo (optionally scaled by 0.125 for
// blocks with blockIdx.x < scale_blocks); else float out.
// ---------------------------------------------------------------------------
template<bool PACKED_OUT>
__global__ __launch_bounds__(256) void gemm_bf16x3(
    const uint32_t* __restrict__ Agh, const uint32_t* __restrict__ Agl,
    const uint32_t* __restrict__ Wgh, const uint32_t* __restrict__ Wgl,
    const float* __restrict__ bias,
    float* __restrict__ Cf, uint32_t* __restrict__ Ch, uint32_t* __restrict__ Cl,
    int N, int scale_blocks)
{
    extern __shared__ uint32_t smg[];
    uint32_t* sAh = smg;            // [2][128][GS]
    uint32_t* sAl = smg + 2 * 128 * GS;
    uint32_t* sBh = smg + 4 * 128 * GS;
    uint32_t* sBl = smg + 6 * 128 * GS;

    const int tid = threadIdx.x;
    const int lane = tid & 31, warp = tid >> 5;
    const int gid = lane >> 2, tig = lane & 3;
    const int wm = warp >> 2, wn = warp & 3;
    const int m0 = blockIdx.y * 128, n0 = blockIdx.x * 128;

    const uint32_t sAh_b = sptr(sAh), sAl_b = sptr(sAl);
    const uint32_t sBh_b = sptr(sBh), sBl_b = sptr(sBl);

    // one stage = 8 cp.async per thread
    auto issue = [&](int st, int k0w) {
#pragma unroll
        for (int i = 0; i < 2; i++) {
            const int c = tid + i * 256;
            const int row = c >> 2, wg = (c & 3) * 4;
            const uint32_t so = (uint32_t)((st * 128 + row) * GS + wg) * 4;
            const size_t ga = (size_t)(m0 + row) * KW + k0w + wg;
            const size_t gb = (size_t)(n0 + row) * KW + k0w + wg;
            cpa16(sAh_b + so, Agh + ga);
            cpa16(sAl_b + so, Agl + ga);
            cpa16(sBh_b + so, Wgh + gb);
            cpa16(sBl_b + so, Wgl + gb);
        }
        cp_commit();
    };

    float acc[4][4][4];
#pragma unroll
    for (int mt = 0; mt < 4; mt++)
#pragma unroll
        for (int nt = 0; nt < 4; nt++)
#pragma unroll
            for (int j = 0; j < 4; j++) acc[mt][nt][j] = 0.0f;

    issue(0, 0);

    for (int kt = 0; kt < 24; kt++) {
        if (kt < 23) issue((kt + 1) & 1, (kt + 1) * 16);
        if (kt < 23) cp_wait1(); else cp_wait0();
        __syncthreads();
        const int st = kt & 1;

#pragma unroll
        for (int ks = 0; ks < 2; ks++) {
            const int kw = ks * 8;
            uint32_t ah[4][4], al[4][4];
#pragma unroll
            for (int mt = 0; mt < 4; mt++) {
                const int r = wm * 64 + mt * 16 + gid;
                const uint32_t* ph = &sAh[(st * 128 + r) * GS];
                const uint32_t* pl = &sAl[(st * 128 + r) * GS];
                ah[mt][0] = ph[kw + tig];          ah[mt][1] = ph[8 * GS + kw + tig];
                ah[mt][2] = ph[kw + tig + 4];      ah[mt][3] = ph[8 * GS + kw + tig + 4];
                al[mt][0] = pl[kw + tig];          al[mt][1] = pl[8 * GS + kw + tig];
                al[mt][2] = pl[kw + tig + 4];      al[mt][3] = pl[8 * GS + kw + tig + 4];
            }
#pragma unroll
            for (int nt = 0; nt < 4; nt++) {
                const int n = wn * 32 + nt * 8 + gid;
                const uint32_t* ph = &sBh[(st * 128 + n) * GS];
                const uint32_t* pl = &sBl[(st * 128 + n) * GS];
                uint32_t bh[2] = {ph[kw + tig], ph[kw + tig + 4]};
                uint32_t bl[2] = {pl[kw + tig], pl[kw + tig + 4]};
#pragma unroll
                for (int mt = 0; mt < 4; mt++) {
                    mma_bf16(acc[mt][nt], al[mt], bh);
                    mma_bf16(acc[mt][nt], ah[mt], bl);
                    mma_bf16(acc[mt][nt], ah[mt], bh);
                }
            }
        }
        __syncthreads();
    }

    // epilogue
    const float scl = (blockIdx.x < scale_blocks) ? 0.125f : 1.0f;
#pragma unroll
    for (int mt = 0; mt < 4; mt++) {
#pragma unroll
        for (int nt = 0; nt < 4; nt++) {
            const int n = n0 + wn * 32 + nt * 8 + tig * 2;
            const float2 bs = *(const float2*)(bias + n);
            const int r = m0 + wm * 64 + mt * 16 + gid;
            const float v0 = (acc[mt][nt][0] + bs.x) * scl;
            const float v1 = (acc[mt][nt][1] + bs.y) * scl;
            const float v2 = (acc[mt][nt][2] + bs.x) * scl;
            const float v3 = (acc[mt][nt][3] + bs.y) * scl;
            if (PACKED_OUT) {
                uint32_t hh, ll;
                size_t w = (size_t)r * (N / 2) + n / 2;
                split2(v0, v1, hh, ll);
                Ch[w] = hh; Cl[w] = ll;
                w = (size_t)(r + 8) * (N / 2) + n / 2;
                split2(v2, v3, hh, ll);
                Ch[w] = hh; Cl[w] = ll;
            } else {
                *(float2*)(Cf + (size_t)r * N + n) = make_float2(v0, v1);
                *(float2*)(Cf + (size_t)(r + 8) * N + n) = make_float2(v2, v3);
            }
        }
    }
}

// ---------------------------------------------------------------------------
// Flash attention, bf16 split x3 mma, packed qkv input, packed output.
// Block = (b, h, 64-q tile), 128 threads / 4 warps (16 rows each).
// Q frags in registers; K/V 2-stage cp.async; P stays in registers
// (C-frag n-pairs == A-frag k-pairs); V via ldmatrix.x2.trans.
// ---------------------------------------------------------------------------
__global__ __launch_bounds__(128) void attn_bf16(
    const uint32_t* __restrict__ Qh, const uint32_t* __restrict__ Ql,
    const float* __restrict__ bias,
    uint32_t* __restrict__ Oh, uint32_t* __restrict__ Ol)
{
    extern __shared__ uint32_t sma[];
    uint32_t* sKh = sma;                    // [2][64][AS]
    uint32_t* sKl = sma + 2 * 64 * AS;
    uint32_t* sVh = sma + 4 * 64 * AS;
    uint32_t* sVl = sma + 6 * 64 * AS;

    const int tid = threadIdx.x;
    const int lane = tid & 31, warp = tid >> 5;
    const int gid = lane >> 2, tig = lane & 3;
    const int qt = blockIdx.x, h = blockIdx.y, b = blockIdx.z;
    const int q0 = qt * 64, wq = warp * 16;

    const uint32_t sKh_b = sptr(sKh), sKl_b = sptr(sKl);
    const uint32_t sVh_b = sptr(sVh), sVl_b = sptr(sVl);

    const int kwbase = DD / 2 + h * 32;        // k-region word base
    const int vwbase = DD + h * 32;            // v-region word base
    const size_t tok0 = (size_t)b * LL;

    auto issue = [&](int st, int kt) {
#pragma unroll
        for (int i = 0; i < 4; i++) {
            const int c = tid + i * 128;
            const int row = c >> 3, wg = (c & 7) * 4;
            const uint32_t so = (uint32_t)((st * 64 + row) * AS + wg) * 4;
            const size_t g = (tok0 + kt * 64 + row) * QKVW + wg;
            cpa16(sKh_b + so, Qh + g + kwbase);
            cpa16(sKl_b + so, Ql + g + kwbase);
            cpa16(sVh_b + so, Qh + g + vwbase);
            cpa16(sVl_b + so, Ql + g + vwbase);
        }
        cp_commit();
    };

    // ---- Q fragments (already scaled & biased in packed qkv) ----
    uint32_t qh[4][4], ql[4][4];
    {
        const uint32_t* r0h = Qh + (tok0 + q0 + wq + gid) * QKVW + h * 32;
        const uint32_t* r1h = r0h + 8 * QKVW;
        const uint32_t* r0l = Ql + (tok0 + q0 + wq + gid) * QKVW + h * 32;
        const uint32_t* r1l = r0l + 8 * QKVW;
#pragma unroll
        for (int ks = 0; ks < 4; ks++) {
            const int kw = ks * 8;
            qh[ks][0] = r0h[kw + tig];     qh[ks][1] = r1h[kw + tig];
            qh[ks][2] = r0h[kw + tig + 4]; qh[ks][3] = r1h[kw + tig + 4];
            ql[ks][0] = r0l[kw + tig];     ql[ks][1] = r1l[kw + tig];
            ql[ks][2] = r0l[kw + tig + 4]; ql[ks][3] = r1l[kw + tig + 4];
        }
    }

    float o[8][4];
#pragma unroll
    for (int dt = 0; dt < 8; dt++)
#pragma unroll
        for (int j = 0; j < 4; j++) o[dt][j] = 0.0f;
    float mr0 = -1e30f, mr1 = -1e30f, lr0 = 0.0f, lr1 = 0.0f;

    const float* bb = bias + ((size_t)(b * HH + h) * LL + q0 + wq) * LL;

    issue(0, 0);

    for (int kt = 0; kt < 16; kt++) {
        if (kt < 15) issue((kt + 1) & 1, kt + 1);
        if (kt < 15) cp_wait1(); else cp_wait0();
        __syncthreads();
        const int st = kt & 1;

        // ---- S = bias ----
        float s[8][4];
#pragma unroll
        for (int nt = 0; nt < 8; nt++) {
            const float* bp = bb + (size_t)gid * LL + kt * 64 + nt * 8 + tig * 2;
            float2 x0 = *(const float2*)bp;
            float2 x1 = *(const float2*)(bp + (size_t)8 * LL);
            s[nt][0] = x0.x; s[nt][1] = x0.y;
            s[nt][2] = x1.x; s[nt][3] = x1.y;
        }

        // ---- S += Q @ K^T ----
#pragma unroll
        for (int ks = 0; ks < 4; ks++) {
            const int kw = ks * 8;
#pragma unroll
            for (int nt = 0; nt < 8; nt++) {
                const uint32_t* ph = &sKh[(st * 64 + nt * 8 + gid) * AS];
                const uint32_t* pl = &sKl[(st * 64 + nt * 8 + gid) * AS];
                uint32_t bh[2] = {ph[kw + tig], ph[kw + tig + 4]};
                uint32_t bl[2] = {pl[kw + tig], pl[kw + tig + 4]};
                mma_bf16(s[nt], ql[ks], bh);
                mma_bf16(s[nt], qh[ks], bl);
                mma_bf16(s[nt], qh[ks], bh);
            }
        }

        // ---- online softmax (rows gid / gid+8) ----
        float mx0 = -1e30f, mx1 = -1e30f;
#pragma unroll
        for (int nt = 0; nt < 8; nt++) {
            mx0 = fmaxf(mx0, fmaxf(s[nt][0], s[nt][1]));
            mx1 = fmaxf(mx1, fmaxf(s[nt][2], s[nt][3]));
        }
        mx0 = fmaxf(mx0, __shfl_xor_sync(0xffffffffu, mx0, 1));
        mx0 = fmaxf(mx0, __shfl_xor_sync(0xffffffffu, mx0, 2));
        mx1 = fmaxf(mx1, __shfl_xor_sync(0xffffffffu, mx1, 1));
        mx1 = fmaxf(mx1, __shfl_xor_sync(0xffffffffu, mx1, 2));
        const float mn0 = fmaxf(mr0, mx0), mn1 = fmaxf(mr1, mx1);
        const float c0 = __expf(mr0 - mn0), c1 = __expf(mr1 - mn1);
        mr0 = mn0; mr1 = mn1;
        float ls0 = 0.0f, ls1 = 0.0f;
#pragma unroll
        for (int nt = 0; nt < 8; nt++) {
            s[nt][0] = __expf(s[nt][0] - mn0);
            s[nt][1] = __expf(s[nt][1] - mn0);
            s[nt][2] = __expf(s[nt][2] - mn1);
            s[nt][3] = __expf(s[nt][3] - mn1);
            ls0 += s[nt][0] + s[nt][1];
            ls1 += s[nt][2] + s[nt][3];
        }
        ls0 += __shfl_xor_sync(0xffffffffu, ls0, 1);
        ls0 += __shfl_xor_sync(0xffffffffu, ls0, 2);
        ls1 += __shfl_xor_sync(0xffffffffu, ls1, 1);
        ls1 += __shfl_xor_sync(0xffffffffu, ls1, 2);
        lr0 = lr0 * c0 + ls0;
        lr1 = lr1 * c1 + ls1;
#pragma unroll
        for (int dt = 0; dt < 8; dt++) {
            o[dt][0] *= c0; o[dt][1] *= c0;
            o[dt][2] *= c1; o[dt][3] *= c1;
        }

        // ---- O += P @ V  (P packed from registers; V via ldmatrix.trans) ----
#pragma unroll
        for (int ks = 0; ks < 4; ks++) {
            uint32_t ph[4], pl[4];
            split2(s[2 * ks][0],     s[2 * ks][1],     ph[0], pl[0]);
            split2(s[2 * ks][2],     s[2 * ks][3],     ph[1], pl[1]);
            split2(s[2 * ks + 1][0], s[2 * ks + 1][1], ph[2], pl[2]);
            split2(s[2 * ks + 1][2], s[2 * ks + 1][3], ph[3], pl[3]);
            const uint32_t rowoff =
                (uint32_t)((st * 64 + 16 * ks + (lane & 15)) * AS) * 4;
#pragma unroll
            for (int dt = 0; dt < 8; dt++) {
                uint32_t vh2[2], vl2[2];
                ldmx2t(vh2[0], vh2[1], sVh_b + rowoff + dt * 16);
                ldmx2t(vl2[0], vl2[1], sVl_b + rowoff + dt * 16);
                mma_bf16(o[dt], pl, vh2);
                mma_bf16(o[dt], ph, vl2);
                mma_bf16(o[dt], ph, vh2);
            }
        }
        __syncthreads();
    }

    // ---- normalize + packed store ----
    const float inv0 = 1.0f / lr0, inv1 = 1.0f / lr1;
#pragma unroll
    for (int dt = 0; dt < 8; dt++) {
        uint32_t hh, ll;
        size_t w = (tok0 + q0 + wq + gid) * OW + h * 32 + dt * 4 + tig;
        split2(o[dt][0] * inv0, o[dt][1] * inv0, hh, ll);
        Oh[w] = hh; Ol[w] = ll;
        w = (tok0 + q0 + wq + 8 + gid) * OW + h * 32 + dt * 4 + tig;
        split2(o[dt][2] * inv1, o[dt][3] * inv1, hh, ll);
        Oh[w] = hh; Ol[w] = ll;
    }
}

// ---------------------------------------------------------------------------
// Launch
// ---------------------------------------------------------------------------
extern "C" void kernel_launch(void* const* d_in, const int* in_sizes, int n_in,
                              void* d_out, int out_size)
{
    const float* x         = (const float*)d_in[0];   // [B, L, D]
    const float* attn_bias = (const float*)d_in[1];   // [B, H, L, L]
    const float* w_in      = (const float*)d_in[2];   // [3D, D]
    const float* b_in      = (const float*)d_in[3];   // [3D]
    const float* w_out     = (const float*)d_in[4];   // [D, D]
    const float* b_out     = (const float*)d_in[5];   // [D]
    float* out = (float*)d_out;                       // [B, L, D]

    uint32_t *xh, *xl, *wih, *wil, *woh, *wol, *qh, *ql, *oh, *ol;
    cudaGetSymbolAddress((void**)&xh,  g_xh);  cudaGetSymbolAddress((void**)&xl,  g_xl);
    cudaGetSymbolAddress((void**)&wih, g_wih); cudaGetSymbolAddress((void**)&wil, g_wil);
    cudaGetSymbolAddress((void**)&woh, g_woh); cudaGetSymbolAddress((void**)&wol, g_wol);
    cudaGetSymbolAddress((void**)&qh,  g_qh);  cudaGetSymbolAddress((void**)&ql,  g_ql);
    cudaGetSymbolAddress((void**)&oh,  g_oh);  cudaGetSymbolAddress((void**)&ol,  g_ol);

    // 0) split-pack prepass
    {
        const int nx = 4096 * KW, nwi = 2304 * KW, nwo = 768 * KW;
        splitpack_kernel<<<(nx + 255) / 256, 256>>>(x, xh, xl, nx);
        splitpack_kernel<<<(nwi + 255) / 256, 256>>>(w_in, wih, wil, nwi);
        splitpack_kernel<<<(nwo + 255) / 256, 256>>>(w_out, woh, wol, nwo);
    }

    const int gemm_smem = 8 * 128 * GS * 4;   // 81920 B
    const int attn_smem = 8 * 64 * AS * 4;    // 73728 B

    // 1) QKV projection -> packed hi/lo, q pre-scaled by 0.125 (blocks 0..5)
    {
        cudaFuncSetAttribute(gemm_bf16x3<true>,
                             cudaFuncAttributeMaxDynamicSharedMemorySize, gemm_smem);
        dim3 grid(2304 / 128, 4096 / 128);
        gemm_bf16x3<true><<<grid, 256, gemm_smem>>>(
            xh, xl, wih, wil, b_in, nullptr, qh, ql, 2304, 6);
    }

    // 2) attention -> packed hi/lo
    {
        cudaFuncSetAttribute(attn_bf16,
                             cudaFuncAttributeMaxDynamicSharedMemorySize, attn_smem);
        dim3 grid(LL / 64, HH, BB);
        attn_bf16<<<grid, 128, attn_smem>>>(qh, ql, attn_bias, oh, ol);
    }

    // 3) output projection -> float out
    {
        cudaFuncSetAttribute(gemm_bf16x3<false>,
                             cudaFuncAttributeMaxDynamicSharedMemorySize, gemm_smem);
        dim3 grid(768 / 128, 4096 / 128);
        gemm_bf16x3<false><<<grid, 256, gemm_smem>>>(
            oh, ol, woh, wol, b_out, out, nullptr, nullptr, 768, 0);
    }
}